// round 10
// baseline (speedup 1.0000x reference)
#include <cuda_runtime.h>

#define FULLMASK 0xffffffffu

constexpr int B = 64;
constexpr int L = 512;
constexpr int R = 1024;
constexpr int A = 14;
constexpr float EPSV = 1e-12f;
constexpr float CUT2 = 25.0f;     // CUTOFF^2

constexpr int LIG_BLOCKS_PER_B = 4;                       // each: 7 off-diag + 2 diag tiles
constexpr int LIG_BLOCKS = B * LIG_BLOCKS_PER_B;          // 256
constexpr int SC_GROUPS_PER_BLOCK = 64;                   // 8 warps x 8 groups
constexpr int SC_BLOCKS = (B * R) / SC_GROUPS_PER_BLOCK;  // 1024
constexpr int GRID = LIG_BLOCKS + SC_BLOCKS;              // 1280 (ligand every 5th block)
constexpr int NSLOT = 32;

// -------- persistent scratch (zeroed at load; finalizer re-zeros each run) --------
__device__ float g_lig_num[B];
__device__ float g_lig_den[B];
__device__ float g_lig_se[B];
__device__ float g_lig_cnt[B];
__device__ float g_slots[4][NSLOT];
__device__ unsigned int g_ticket;

// off-diagonal tile pair table: (a<<4)|b for 0<=a<b<8, 28 entries
__constant__ unsigned char c_tpairs[28] = {
    0x01,0x02,0x03,0x04,0x05,0x06,0x07,
    0x12,0x13,0x14,0x15,0x16,0x17,
    0x23,0x24,0x25,0x26,0x27,
    0x34,0x35,0x36,0x37,
    0x45,0x46,0x47,
    0x56,0x57,
    0x67
};

__device__ __forceinline__ float fast_sqrt(float x) {
    float r;
    asm("sqrt.approx.f32 %0, %1;" : "=f"(r) : "f"(x));
    return r;
}

// i-side pre-scaled: Pi.xyz = -2*coord, Pi.w = |coord|^2 ; j-side raw (w = norm).
// psq = wi + wj - 2*dot  via pure fma chain.
__device__ __forceinline__ void pair_acc2(
    const float4& Pi, const float4& Ti,
    const float4& pj, const float4& tj,
    float& num, float& den)
{
    float c = Pi.w + pj.w;
    c = fmaf(Pi.x, pj.x, c); c = fmaf(Pi.y, pj.y, c); c = fmaf(Pi.z, pj.z, c);   // psq
    float d = Ti.w + tj.w;
    d = fmaf(Ti.x, tj.x, d); d = fmaf(Ti.y, tj.y, d); d = fmaf(Ti.z, tj.z, d);   // tsq
    float pe = fmaxf(c, EPSV);
    float te = fmaxf(d, EPSV);
    float v = (pe + te) - 2.f * fast_sqrt(pe * te);   // (pd - td)^2
    if (d <= CUT2) { num += v; den += 1.f; }          // d>0 structurally (masked pts pushed far)
}

__device__ __forceinline__ float4 scale_i(const float4& a) {
    return make_float4(-2.f*a.x, -2.f*a.y, -2.f*a.z, a.w);
}

__global__ void __launch_bounds__(256) fused_kernel(
    const float* __restrict__ lp, const float* __restrict__ lt,
    const float* __restrict__ scp, const float* __restrict__ sct,
    const unsigned int* __restrict__ lm, const unsigned int* __restrict__ am,
    float* __restrict__ out, int out_size)
{
    __shared__ float4 s_p[L];     // 8 KB
    __shared__ float4 s_t[L];     // 8 KB
    __shared__ float4 wr[8];
    __shared__ float bacc[4];
    __shared__ unsigned int s_islast;
    __shared__ float fin[3][2];
    __shared__ float sl[4];

    const int t = threadIdx.x;
    const int bid = blockIdx.x;
    const int lane = t & 31;
    const bool is_lig = (bid % 5) == 0;     // interleave ligand blocks across the grid

    if (is_lig) {
        // ======================= ligand =======================
        const int lbid = bid / 5;           // 0..255
        const int b = lbid >> 2;
        const int r = lbid & 3;
        const float* P = lp + (size_t)b * L * 3;
        const float* T = lt + (size_t)b * L * 3;
        const unsigned int* M = lm + (size_t)b * L;

        float num = 0.f, den = 0.f, se = 0.f, cnt = 0.f;

        // fill all 512 points once; r==0 also does the coord MSE
        for (int j = t; j < L; j += 256) {
            float px = P[j*3+0], py = P[j*3+1], pz = P[j*3+2];
            float tx = T[j*3+0], ty = T[j*3+1], tz = T[j*3+2];
            bool m = (M[j] != 0u);
            if (r == 0 && m) {
                float dx = px - tx, dy = py - ty, dz = pz - tz;
                se  += dx*dx + dy*dy + dz*dz;
                cnt += 1.f;
            }
            if (!m) tx += 1e4f + 64.f * (float)j;   // push invalid targets apart
            s_p[j] = make_float4(px, py, pz, px*px + py*py + pz*pz);
            s_t[j] = make_float4(tx, ty, tz, tx*tx + ty*ty + tz*tz);
        }
        __syncthreads();   // smem read-only from here on

        // ---- 7 off-diagonal 64x64 tile combos ----
        #pragma unroll 1
        for (int c = 7*r; c < 7*r + 7; ++c) {
            const int code = c_tpairs[c];
            const int ta = code >> 4, tb = code & 15;
            const int i0 = ta*64 + (t & 15);
            float4 Pi[4], Ti[4];
            #pragma unroll
            for (int u = 0; u < 4; ++u) {
                Pi[u] = scale_i(s_p[i0 + 16*u]);
                Ti[u] = scale_i(s_t[i0 + 16*u]);
            }
            const int jb = tb*64 + (t >> 4);
            #pragma unroll
            for (int it = 0; it < 4; ++it) {
                float4 pj = s_p[jb + 16*it];
                float4 tj = s_t[jb + 16*it];
                #pragma unroll
                for (int u = 0; u < 4; ++u)
                    pair_acc2(Pi[u], Ti[u], pj, tj, num, den);
            }
        }

        // ---- 2 diagonal tiles: round-robin within 64 ----
        #pragma unroll 1
        for (int dt_ = 2*r; dt_ < 2*r + 2; ++dt_) {
            const int base = dt_ * 64;
            const int il   = t & 63;
            const int off  = t >> 6;
            const float4 pi = scale_i(s_p[base + il]);
            const float4 ti = scale_i(s_t[base + il]);
            #pragma unroll
            for (int k = 1 + off; k <= 32; k += 4) {
                if (k == 32 && il >= 32) break;
                int j = base + ((il + k) & 63);
                pair_acc2(pi, ti, s_p[j], s_t[j], num, den);
            }
        }

        // block reduce 4 vars -> per-batch atomics
        #pragma unroll
        for (int s = 16; s > 0; s >>= 1) {
            num += __shfl_down_sync(FULLMASK, num, s);
            den += __shfl_down_sync(FULLMASK, den, s);
            se  += __shfl_down_sync(FULLMASK, se,  s);
            cnt += __shfl_down_sync(FULLMASK, cnt, s);
        }
        if (lane == 0) wr[t >> 5] = make_float4(num, den, se, cnt);
        __syncthreads();
        if (t < 8) {
            float4 v4 = wr[t];
            float a0 = v4.x, a1 = v4.y, a2 = v4.z, a3 = v4.w;
            #pragma unroll
            for (int s = 4; s > 0; s >>= 1) {
                a0 += __shfl_down_sync(0xffu, a0, s);
                a1 += __shfl_down_sync(0xffu, a1, s);
                a2 += __shfl_down_sync(0xffu, a2, s);
                a3 += __shfl_down_sync(0xffu, a3, s);
            }
            if (t == 0) {
                atomicAdd(&g_lig_num[b], a0);
                atomicAdd(&g_lig_den[b], a1);
                atomicAdd(&g_lig_se[b],  a2);
                atomicAdd(&g_lig_cnt[b], a3);
            }
        }
    } else {
        // ======================= sidechain (shfl-based, 8 groups/warp) =======================
        if (t < 4) bacc[t] = 0.f;
        __syncthreads();

        const int scbid = bid - bid / 5 - 1;   // 0..1023
        const int w = t >> 5;
        const int h = (lane >> 4);          // half-warp id
        const int a = lane & 15;            // atom slot
        const bool av = a < A;
        const unsigned int gbase = (unsigned int)scbid * SC_GROUPS_PER_BLOCK + w * 8;

        float acc_gs = 0.f, acc_gc = 0.f, acc_mnum = 0.f, acc_mden = 0.f;

        #pragma unroll 2
        for (int it2 = 0; it2 < 4; ++it2) {
            const unsigned int g = gbase + it2 * 2 + h;

            float px=0.f, py=0.f, pz=0.f, tx=0.f, ty=0.f, tz=0.f;
            float m = 0.f, mnum = 0.f;
            if (av) {
                const float* Pg = scp + (size_t)g * (A*3) + a*3;
                const float* Tg = sct + (size_t)g * (A*3) + a*3;
                px = Pg[0]; py = Pg[1]; pz = Pg[2];
                tx = Tg[0]; ty = Tg[1]; tz = Tg[2];
                m = (am[(size_t)g * A + a] != 0u) ? 1.f : 0.f;
                float dx = px - tx, dy = py - ty, dz = pz - tz;
                mnum = m * (dx*dx + dy*dy + dz*dz) * (1.f/3.f);
                if (m == 0.f) tx += 1e3f + 48.f * (float)a;
            }
            const unsigned int bal = __ballot_sync(FULLMASK, av && m != 0.f);
            float pw = px*px + py*py + pz*pz;
            float tw = tx*tx + ty*ty + tz*tz;
            // i-side -2x pre-scale (own atom)
            float Mpx = -2.f*px, Mpy = -2.f*py, Mpz = -2.f*pz;
            float Mtx = -2.f*tx, Mty = -2.f*ty, Mtz = -2.f*tz;

            float num = 0.f, den = 0.f;
            int j = a;
            #pragma unroll
            for (int d = 1; d <= 7; ++d) {
                j = (j + 1 == A) ? 0 : j + 1;          // (a+d) mod 14
                int src = (lane & 16) | j;
                float qx = __shfl_sync(FULLMASK, px, src);
                float qy = __shfl_sync(FULLMASK, py, src);
                float qz = __shfl_sync(FULLMASK, pz, src);
                float qw = __shfl_sync(FULLMASK, pw, src);
                float sx = __shfl_sync(FULLMASK, tx, src);
                float sy = __shfl_sync(FULLMASK, ty, src);
                float sz = __shfl_sync(FULLMASK, tz, src);
                float sw = __shfl_sync(FULLMASK, tw, src);
                float c = pw + qw;
                c = fmaf(Mpx, qx, c); c = fmaf(Mpy, qy, c); c = fmaf(Mpz, qz, c);  // psq
                float dd = tw + sw;
                dd = fmaf(Mtx, sx, dd); dd = fmaf(Mty, sy, dd); dd = fmaf(Mtz, sz, dd); // tsq
                float pe = fmaxf(c, EPSV);
                float te = fmaxf(dd, EPSV);
                float v = (pe + te) - 2.f * fast_sqrt(pe * te);
                bool act = (d < 7) ? av : (a < 7);
                if (act && dd <= CUT2) { num += v; den += 1.f; }
            }

            // reduce within each 16-lane segment
            #pragma unroll
            for (int s = 8; s > 0; s >>= 1) {
                num  += __shfl_down_sync(FULLMASK, num,  s, 16);
                den  += __shfl_down_sync(FULLMASK, den,  s, 16);
                mnum += __shfl_down_sync(FULLMASK, mnum, s, 16);
            }
            float gs = 0.f, gc = 0.f;
            if (a == 0 && den > 0.f) { gs = num / den; gc = 1.f; }
            gs   += __shfl_down_sync(FULLMASK, gs,   16);
            gc   += __shfl_down_sync(FULLMASK, gc,   16);
            mnum += __shfl_down_sync(FULLMASK, mnum, 16);
            if (lane == 0) {
                acc_gs   += gs;
                acc_gc   += gc;
                acc_mnum += mnum;
                acc_mden += (float)__popc(bal);
            }
        }

        if (lane == 0) {
            atomicAdd(&bacc[0], acc_gs);
            atomicAdd(&bacc[1], acc_gc);
            atomicAdd(&bacc[2], acc_mnum);
            atomicAdd(&bacc[3], acc_mden);
        }
        __syncthreads();
        if (t < 4) atomicAdd(&g_slots[t][bid & (NSLOT - 1)], bacc[t]);
    }

    // ======================= last-block finalization =======================
    __threadfence();
    if (t == 0) s_islast = (atomicAdd(&g_ticket, 1u) == (unsigned)(GRID - 1)) ? 1u : 0u;
    __syncthreads();
    if (!s_islast) return;

    float lig = 0.f, ld = 0.f, has = 0.f;
    if (t < B) {
        float sev = __ldcg(&g_lig_se[t]);
        float cn  = __ldcg(&g_lig_cnt[t]);
        float nu  = __ldcg(&g_lig_num[t]);
        float de  = __ldcg(&g_lig_den[t]);
        lig = sev / (3.f * fmaxf(cn, 1.f));
        if (de > 0.f) { ld = nu / de; has = 1.f; }
    }
    #pragma unroll
    for (int s = 16; s > 0; s >>= 1) {
        lig += __shfl_down_sync(FULLMASK, lig, s);
        ld  += __shfl_down_sync(FULLMASK, ld,  s);
        has += __shfl_down_sync(FULLMASK, has, s);
    }
    if (lane == 0 && t < B) { fin[0][t>>5] = lig; fin[1][t>>5] = ld; fin[2][t>>5] = has; }

    if (t < NSLOT) {
        float s0 = __ldcg(&g_slots[0][t]);
        float s1 = __ldcg(&g_slots[1][t]);
        float s2 = __ldcg(&g_slots[2][t]);
        float s3 = __ldcg(&g_slots[3][t]);
        #pragma unroll
        for (int s = 16; s > 0; s >>= 1) {
            s0 += __shfl_down_sync(FULLMASK, s0, s);
            s1 += __shfl_down_sync(FULLMASK, s1, s);
            s2 += __shfl_down_sync(FULLMASK, s2, s);
            s3 += __shfl_down_sync(FULLMASK, s3, s);
        }
        if (t == 0) { sl[0] = s0; sl[1] = s1; sl[2] = s2; sl[3] = s3; }
    }
    __syncthreads();

    // reset scratch for next graph replay
    if (t < B) {
        g_lig_num[t] = 0.f; g_lig_den[t] = 0.f;
        g_lig_se[t]  = 0.f; g_lig_cnt[t] = 0.f;
    }
    if (t < 4 * NSLOT) g_slots[t >> 5][t & (NSLOT - 1)] = 0.f;
    if (t == 1) g_ticket = 0u;

    if (t == 0) {
        float ligand_loss = (fin[0][0] + fin[0][1]) * (1.f / 64.f);
        float hs = fin[2][0] + fin[2][1];
        float ligand_dist = (fin[1][0] + fin[1][1]) / fmaxf(hs, 1.f);
        float sc  = sl[2] / fmaxf(sl[3], 1.f);
        float scd = sl[0] / fmaxf(sl[1], 1.f);
        float total = ligand_loss + 0.2f * ligand_dist + 0.5f * sc + 0.1f * scd;
        for (int k = 0; k < out_size; ++k) out[k] = total;
    }
}

extern "C" void kernel_launch(void* const* d_in, const int* in_sizes, int n_in,
                              void* d_out, int out_size) {
    const float* lp  = (const float*)d_in[0];
    const float* lt  = (const float*)d_in[1];
    const float* scp = (const float*)d_in[2];
    const float* sct = (const float*)d_in[3];
    const unsigned int* lm = (const unsigned int*)d_in[4];
    const unsigned int* am = (const unsigned int*)d_in[5];
    (void)in_sizes; (void)n_in;

    fused_kernel<<<GRID, 256>>>(lp, lt, scp, sct, lm, am, (float*)d_out, out_size);
}

// round 11
// speedup vs baseline: 1.0087x; 1.0087x over previous
#include <cuda_runtime.h>

#define FULLMASK 0xffffffffu

constexpr int B = 64;
constexpr int L = 512;
constexpr int R = 1024;
constexpr int A = 14;
constexpr float EPSV = 1e-12f;
constexpr float CUT2 = 25.0f;     // CUTOFF^2

constexpr int LIG_BLOCKS_PER_B = 4;                       // each does 7 off-diag + 2 diag tiles
constexpr int LIG_BLOCKS = B * LIG_BLOCKS_PER_B;          // 256
constexpr int SC_GROUPS_PER_BLOCK = 64;                   // 8 warps x 8 groups
constexpr int SC_BLOCKS = (B * R) / SC_GROUPS_PER_BLOCK;  // 1024
constexpr int GRID = LIG_BLOCKS + SC_BLOCKS;              // 1280
constexpr int NSLOT = 32;

// -------- persistent scratch (zeroed at load; finalizer re-zeros each run) --------
__device__ float g_lig_num[B];
__device__ float g_lig_den[B];
__device__ float g_lig_se[B];
__device__ float g_lig_cnt[B];
__device__ float g_slots[4][NSLOT];
__device__ unsigned int g_ticket;

// off-diagonal tile pair table: (a<<4)|b for 0<=a<b<8, 28 entries
__constant__ unsigned char c_tpairs[28] = {
    0x01,0x02,0x03,0x04,0x05,0x06,0x07,
    0x12,0x13,0x14,0x15,0x16,0x17,
    0x23,0x24,0x25,0x26,0x27,
    0x34,0x35,0x36,0x37,
    0x45,0x46,0x47,
    0x56,0x57,
    0x67
};

__device__ __forceinline__ float fast_sqrt(float x) {
    float r;
    asm("sqrt.approx.f32 %0, %1;" : "=f"(r) : "f"(x));
    return r;
}

// (pd - td)^2 from Gram terms; accumulate when target dist in (0, CUTOFF]
__device__ __forceinline__ void pair_acc(
    const float4& pi, const float4& ti, const float4& pj, const float4& tj,
    float& num, float& den)
{
    float dp = pi.x*pj.x; dp = fmaf(pi.y, pj.y, dp); dp = fmaf(pi.z, pj.z, dp);
    float dt = ti.x*tj.x; dt = fmaf(ti.y, tj.y, dt); dt = fmaf(ti.z, tj.z, dt);
    float psq = fmaf(-2.f, dp, pi.w + pj.w);
    float tsq = fmaf(-2.f, dt, ti.w + tj.w);
    float pe = fmaxf(psq, EPSV);
    float v = (pe + tsq) - 2.f * fast_sqrt(pe * tsq);
    if (tsq > 0.f && tsq <= CUT2) { num += v; den += 1.f; }
}

__global__ void __launch_bounds__(256, 5) fused_kernel(
    const float* __restrict__ lp, const float* __restrict__ lt,
    const float* __restrict__ scp, const float* __restrict__ sct,
    const unsigned int* __restrict__ lm, const unsigned int* __restrict__ am,
    float* __restrict__ out, int out_size)
{
    __shared__ float4 s_p[L];     // 8 KB
    __shared__ float4 s_t[L];     // 8 KB
    __shared__ float4 wr[8];
    __shared__ float bacc[4];
    __shared__ unsigned int s_islast;
    __shared__ float fin[3][2];
    __shared__ float sl[4];

    const int t = threadIdx.x;
    const int bid = blockIdx.x;
    const int lane = t & 31;

    if (bid < LIG_BLOCKS) {
        // ======================= ligand =======================
        const int b = bid >> 2;
        const int r = bid & 3;
        const float* P = lp + (size_t)b * L * 3;
        const float* T = lt + (size_t)b * L * 3;
        const unsigned int* M = lm + (size_t)b * L;

        float num = 0.f, den = 0.f, se = 0.f, cnt = 0.f;

        // fill all 512 points once; r==0 also does the coord MSE
        for (int j = t; j < L; j += 256) {
            float px = P[j*3+0], py = P[j*3+1], pz = P[j*3+2];
            float tx = T[j*3+0], ty = T[j*3+1], tz = T[j*3+2];
            bool m = (M[j] != 0u);
            if (r == 0 && m) {
                float dx = px - tx, dy = py - ty, dz = pz - tz;
                se  += dx*dx + dy*dy + dz*dz;
                cnt += 1.f;
            }
            if (!m) tx += 1e4f + 64.f * (float)j;   // push invalid targets apart
            s_p[j] = make_float4(px, py, pz, px*px + py*py + pz*pz);
            s_t[j] = make_float4(tx, ty, tz, tx*tx + ty*ty + tz*tz);
        }
        __syncthreads();   // smem read-only from here on

        // ---- 7 off-diagonal 64x64 tile combos ----
        #pragma unroll 1
        for (int c = 7*r; c < 7*r + 7; ++c) {
            const int code = c_tpairs[c];
            const int ta = code >> 4, tb = code & 15;
            const int i0 = ta*64 + (t & 15);
            float4 Pi[4], Ti[4];
            #pragma unroll
            for (int u = 0; u < 4; ++u) {
                Pi[u] = s_p[i0 + 16*u];
                Ti[u] = s_t[i0 + 16*u];
            }
            const int jb = tb*64 + (t >> 4);
            #pragma unroll
            for (int it = 0; it < 4; ++it) {
                float4 pj = s_p[jb + 16*it];
                float4 tj = s_t[jb + 16*it];
                #pragma unroll
                for (int u = 0; u < 4; ++u)
                    pair_acc(Pi[u], Ti[u], pj, tj, num, den);
            }
        }

        // ---- 2 diagonal tiles: round-robin within 64 ----
        #pragma unroll 1
        for (int dt_ = 2*r; dt_ < 2*r + 2; ++dt_) {
            const int base = dt_ * 64;
            const int il   = t & 63;
            const int off  = t >> 6;
            const float4 pi = s_p[base + il];
            const float4 ti = s_t[base + il];
            #pragma unroll
            for (int k = 1 + off; k <= 32; k += 4) {
                if (k == 32 && il >= 32) break;
                int j = base + ((il + k) & 63);
                pair_acc(pi, ti, s_p[j], s_t[j], num, den);
            }
        }

        // block reduce 4 vars -> per-batch atomics
        #pragma unroll
        for (int s = 16; s > 0; s >>= 1) {
            num += __shfl_down_sync(FULLMASK, num, s);
            den += __shfl_down_sync(FULLMASK, den, s);
            se  += __shfl_down_sync(FULLMASK, se,  s);
            cnt += __shfl_down_sync(FULLMASK, cnt, s);
        }
        if (lane == 0) wr[t >> 5] = make_float4(num, den, se, cnt);
        __syncthreads();
        if (t < 8) {
            float4 v4 = wr[t];
            float a0 = v4.x, a1 = v4.y, a2 = v4.z, a3 = v4.w;
            #pragma unroll
            for (int s = 4; s > 0; s >>= 1) {
                a0 += __shfl_down_sync(0xffu, a0, s);
                a1 += __shfl_down_sync(0xffu, a1, s);
                a2 += __shfl_down_sync(0xffu, a2, s);
                a3 += __shfl_down_sync(0xffu, a3, s);
            }
            if (t == 0) {
                atomicAdd(&g_lig_num[b], a0);
                atomicAdd(&g_lig_den[b], a1);
                atomicAdd(&g_lig_se[b],  a2);
                atomicAdd(&g_lig_cnt[b], a3);
            }
        }
    } else {
        // ======================= sidechain (shfl-based, 8 groups/warp) =======================
        if (t < 4) bacc[t] = 0.f;
        __syncthreads();

        const int w = t >> 5;
        const int h = (lane >> 4);          // half-warp id
        const int a = lane & 15;            // atom slot
        const bool av = a < A;
        const unsigned int gbase = (unsigned int)(bid - LIG_BLOCKS) * SC_GROUPS_PER_BLOCK + w * 8;

        float acc_gs = 0.f, acc_gc = 0.f, acc_mnum = 0.f, acc_mden = 0.f;

        #pragma unroll 1
        for (int it2 = 0; it2 < 4; ++it2) {
            const unsigned int g = gbase + it2 * 2 + h;

            float px=0.f, py=0.f, pz=0.f, tx=0.f, ty=0.f, tz=0.f;
            float m = 0.f, mnum = 0.f;
            if (av) {
                const float* Pg = scp + (size_t)g * (A*3) + a*3;
                const float* Tg = sct + (size_t)g * (A*3) + a*3;
                px = Pg[0]; py = Pg[1]; pz = Pg[2];
                tx = Tg[0]; ty = Tg[1]; tz = Tg[2];
                m = (am[(size_t)g * A + a] != 0u) ? 1.f : 0.f;
                float dx = px - tx, dy = py - ty, dz = pz - tz;
                mnum = m * (dx*dx + dy*dy + dz*dz) * (1.f/3.f);
                if (m == 0.f) tx += 1e3f + 48.f * (float)a;
            }
            const unsigned int bal = __ballot_sync(FULLMASK, av && m != 0.f);
            float pw = px*px + py*py + pz*pz;
            float tw = tx*tx + ty*ty + tz*tz;

            float num = 0.f, den = 0.f;
            int j = a;
            #pragma unroll
            for (int d = 1; d <= 7; ++d) {
                j = (j + 1 == A) ? 0 : j + 1;          // (a+d) mod 14
                int src = (lane & 16) | j;
                float qx = __shfl_sync(FULLMASK, px, src);
                float qy = __shfl_sync(FULLMASK, py, src);
                float qz = __shfl_sync(FULLMASK, pz, src);
                float qw = __shfl_sync(FULLMASK, pw, src);
                float sx = __shfl_sync(FULLMASK, tx, src);
                float sy = __shfl_sync(FULLMASK, ty, src);
                float sz = __shfl_sync(FULLMASK, tz, src);
                float sw = __shfl_sync(FULLMASK, tw, src);
                float dp = px*qx; dp = fmaf(py, qy, dp); dp = fmaf(pz, qz, dp);
                float dt = tx*sx; dt = fmaf(ty, sy, dt); dt = fmaf(tz, sz, dt);
                float psq = fmaf(-2.f, dp, pw + qw);
                float tsq = fmaf(-2.f, dt, tw + sw);
                float pe = fmaxf(psq, EPSV);
                float v = (pe + tsq) - 2.f * fast_sqrt(pe * tsq);
                bool act = (d < 7) ? av : (a < 7);
                if (act && tsq > 0.f && tsq <= CUT2) { num += v; den += 1.f; }
            }

            // reduce within each 16-lane segment
            #pragma unroll
            for (int s = 8; s > 0; s >>= 1) {
                num  += __shfl_down_sync(FULLMASK, num,  s, 16);
                den  += __shfl_down_sync(FULLMASK, den,  s, 16);
                mnum += __shfl_down_sync(FULLMASK, mnum, s, 16);
            }
            float gs = 0.f, gc = 0.f;
            if (a == 0 && den > 0.f) { gs = num / den; gc = 1.f; }
            gs   += __shfl_down_sync(FULLMASK, gs,   16);
            gc   += __shfl_down_sync(FULLMASK, gc,   16);
            mnum += __shfl_down_sync(FULLMASK, mnum, 16);
            if (lane == 0) {
                acc_gs   += gs;
                acc_gc   += gc;
                acc_mnum += mnum;
                acc_mden += (float)__popc(bal);
            }
        }

        if (lane == 0) {
            atomicAdd(&bacc[0], acc_gs);
            atomicAdd(&bacc[1], acc_gc);
            atomicAdd(&bacc[2], acc_mnum);
            atomicAdd(&bacc[3], acc_mden);
        }
        __syncthreads();
        if (t < 4) atomicAdd(&g_slots[t][bid & (NSLOT - 1)], bacc[t]);
    }

    // ======================= last-block finalization =======================
    __threadfence();
    if (t == 0) s_islast = (atomicAdd(&g_ticket, 1u) == (unsigned)(GRID - 1)) ? 1u : 0u;
    __syncthreads();
    if (!s_islast) return;

    float lig = 0.f, ld = 0.f, has = 0.f;
    if (t < B) {
        float sev = __ldcg(&g_lig_se[t]);
        float cn  = __ldcg(&g_lig_cnt[t]);
        float nu  = __ldcg(&g_lig_num[t]);
        float de  = __ldcg(&g_lig_den[t]);
        lig = sev / (3.f * fmaxf(cn, 1.f));
        if (de > 0.f) { ld = nu / de; has = 1.f; }
    }
    #pragma unroll
    for (int s = 16; s > 0; s >>= 1) {
        lig += __shfl_down_sync(FULLMASK, lig, s);
        ld  += __shfl_down_sync(FULLMASK, ld,  s);
        has += __shfl_down_sync(FULLMASK, has, s);
    }
    if (lane == 0 && t < B) { fin[0][t>>5] = lig; fin[1][t>>5] = ld; fin[2][t>>5] = has; }

    if (t < NSLOT) {
        float s0 = __ldcg(&g_slots[0][t]);
        float s1 = __ldcg(&g_slots[1][t]);
        float s2 = __ldcg(&g_slots[2][t]);
        float s3 = __ldcg(&g_slots[3][t]);
        #pragma unroll
        for (int s = 16; s > 0; s >>= 1) {
            s0 += __shfl_down_sync(FULLMASK, s0, s);
            s1 += __shfl_down_sync(FULLMASK, s1, s);
            s2 += __shfl_down_sync(FULLMASK, s2, s);
            s3 += __shfl_down_sync(FULLMASK, s3, s);
        }
        if (t == 0) { sl[0] = s0; sl[1] = s1; sl[2] = s2; sl[3] = s3; }
    }
    __syncthreads();

    // reset scratch for next graph replay
    if (t < B) {
        g_lig_num[t] = 0.f; g_lig_den[t] = 0.f;
        g_lig_se[t]  = 0.f; g_lig_cnt[t] = 0.f;
    }
    if (t < 4 * NSLOT) g_slots[t >> 5][t & (NSLOT - 1)] = 0.f;
    if (t == 1) g_ticket = 0u;

    if (t == 0) {
        float ligand_loss = (fin[0][0] + fin[0][1]) * (1.f / 64.f);
        float hs = fin[2][0] + fin[2][1];
        float ligand_dist = (fin[1][0] + fin[1][1]) / fmaxf(hs, 1.f);
        float sc  = sl[2] / fmaxf(sl[3], 1.f);
        float scd = sl[0] / fmaxf(sl[1], 1.f);
        float total = ligand_loss + 0.2f * ligand_dist + 0.5f * sc + 0.1f * scd;
        for (int k = 0; k < out_size; ++k) out[k] = total;
    }
}

extern "C" void kernel_launch(void* const* d_in, const int* in_sizes, int n_in,
                              void* d_out, int out_size) {
    const float* lp  = (const float*)d_in[0];
    const float* lt  = (const float*)d_in[1];
    const float* scp = (const float*)d_in[2];
    const float* sct = (const float*)d_in[3];
    const unsigned int* lm = (const unsigned int*)d_in[4];
    const unsigned int* am = (const unsigned int*)d_in[5];
    (void)in_sizes; (void)n_in;

    fused_kernel<<<GRID, 256>>>(lp, lt, scp, sct, lm, am, (float*)d_out, out_size);
}

// round 12
// speedup vs baseline: 1.1405x; 1.1306x over previous
#include <cuda_runtime.h>

#define FULLMASK 0xffffffffu

constexpr int B = 64;
constexpr int L = 512;
constexpr int R = 1024;
constexpr int A = 14;
constexpr float EPSV = 1e-12f;
constexpr float CUT2 = 25.0f;     // CUTOFF^2

constexpr int LIG_BLOCKS_PER_B = 4;                       // each does 7 off-diag + 2 diag tiles
constexpr int LIG_BLOCKS = B * LIG_BLOCKS_PER_B;          // 256
constexpr int SC_GROUPS_PER_BLOCK = 64;                   // 8 warps x 8 groups
constexpr int SC_BLOCKS = (B * R) / SC_GROUPS_PER_BLOCK;  // 1024
constexpr int GRID = LIG_BLOCKS + SC_BLOCKS;              // 1280
constexpr int NSLOT = 32;

// -------- persistent scratch (zeroed at load; finalizer re-zeros each run) --------
__device__ float g_lig_num[B];
__device__ float g_lig_den[B];
__device__ float g_lig_se[B];
__device__ float g_lig_cnt[B];
__device__ float g_slots[4][NSLOT];
__device__ unsigned int g_ticket;

// off-diagonal tile pair table: (a<<4)|b for 0<=a<b<8, 28 entries
__constant__ unsigned char c_tpairs[28] = {
    0x01,0x02,0x03,0x04,0x05,0x06,0x07,
    0x12,0x13,0x14,0x15,0x16,0x17,
    0x23,0x24,0x25,0x26,0x27,
    0x34,0x35,0x36,0x37,
    0x45,0x46,0x47,
    0x56,0x57,
    0x67
};

__device__ __forceinline__ float fast_sqrt(float x) {
    float r;
    asm("sqrt.approx.f32 %0, %1;" : "=f"(r) : "f"(x));
    return r;
}

// (pd - td)^2 from Gram terms; accumulate when target dist in (0, CUTOFF]
__device__ __forceinline__ void pair_acc(
    const float4& pi, const float4& ti, const float4& pj, const float4& tj,
    float& num, float& den)
{
    float dp = pi.x*pj.x; dp = fmaf(pi.y, pj.y, dp); dp = fmaf(pi.z, pj.z, dp);
    float dt = ti.x*tj.x; dt = fmaf(ti.y, tj.y, dt); dt = fmaf(ti.z, tj.z, dt);
    float psq = fmaf(-2.f, dp, pi.w + pj.w);
    float tsq = fmaf(-2.f, dt, ti.w + tj.w);
    float pe = fmaxf(psq, EPSV);
    float v = (pe + tsq) - 2.f * fast_sqrt(pe * tsq);
    if (tsq > 0.f && tsq <= CUT2) { num += v; den += 1.f; }
}

__global__ void __launch_bounds__(256, 5) fused_kernel(
    const float* __restrict__ lp, const float* __restrict__ lt,
    const float* __restrict__ scp, const float* __restrict__ sct,
    const unsigned int* __restrict__ lm, const unsigned int* __restrict__ am,
    float* __restrict__ out, int out_size)
{
    __shared__ float4 s_p[L];     // 8 KB
    __shared__ float4 s_t[L];     // 8 KB
    __shared__ float4 wr[8];
    __shared__ float bacc[4];
    __shared__ unsigned int s_islast;
    __shared__ float fin[3][2];
    __shared__ float sl[4];

    const int t = threadIdx.x;
    const int bid = blockIdx.x;
    const int lane = t & 31;
    const int w = t >> 5;

    if (bid < LIG_BLOCKS) {
        // ======================= ligand =======================
        const int b = bid >> 2;
        const int r = bid & 3;
        const float* P = lp + (size_t)b * L * 3;
        const float* T = lt + (size_t)b * L * 3;
        const unsigned int* M = lm + (size_t)b * L;

        float num = 0.f, den = 0.f, se = 0.f, cnt = 0.f;

        // fill all 512 points once; r==0 also does the coord MSE
        for (int j = t; j < L; j += 256) {
            float px = P[j*3+0], py = P[j*3+1], pz = P[j*3+2];
            float tx = T[j*3+0], ty = T[j*3+1], tz = T[j*3+2];
            bool m = (M[j] != 0u);
            if (r == 0 && m) {
                float dx = px - tx, dy = py - ty, dz = pz - tz;
                se  += dx*dx + dy*dy + dz*dz;
                cnt += 1.f;
            }
            if (!m) tx += 1e4f + 64.f * (float)j;   // push invalid targets apart
            s_p[j] = make_float4(px, py, pz, px*px + py*py + pz*pz);
            s_t[j] = make_float4(tx, ty, tz, tx*tx + ty*ty + tz*tz);
        }
        __syncthreads();   // smem read-only from here on

        // ---- 7 off-diagonal 64x64 tile combos (2i x 8j, broadcast j) ----
        #pragma unroll 1
        for (int c = 7*r; c < 7*r + 7; ++c) {
            const int code = c_tpairs[c];
            const int ta = code >> 4, tb = code & 15;
            const int ia = ta*64 + lane;
            const float4 Pi0 = s_p[ia],      Ti0 = s_t[ia];
            const float4 Pi1 = s_p[ia + 32], Ti1 = s_t[ia + 32];
            const int jb = tb*64 + w;       // warp-uniform j -> broadcast LDS
            #pragma unroll
            for (int it = 0; it < 8; ++it) {
                float4 pj = s_p[jb + 8*it];
                float4 tj = s_t[jb + 8*it];
                pair_acc(Pi0, Ti0, pj, tj, num, den);
                pair_acc(Pi1, Ti1, pj, tj, num, den);
            }
        }

        // ---- 2 diagonal tiles: round-robin within 64 ----
        #pragma unroll 1
        for (int dt_ = 2*r; dt_ < 2*r + 2; ++dt_) {
            const int base = dt_ * 64;
            const int il   = t & 63;
            const int off  = t >> 6;
            const float4 pi = s_p[base + il];
            const float4 ti = s_t[base + il];
            #pragma unroll
            for (int k = 1 + off; k <= 32; k += 4) {
                if (k == 32 && il >= 32) break;
                int j = base + ((il + k) & 63);
                pair_acc(pi, ti, s_p[j], s_t[j], num, den);
            }
        }

        // block reduce 4 vars -> per-batch atomics
        #pragma unroll
        for (int s = 16; s > 0; s >>= 1) {
            num += __shfl_down_sync(FULLMASK, num, s);
            den += __shfl_down_sync(FULLMASK, den, s);
            se  += __shfl_down_sync(FULLMASK, se,  s);
            cnt += __shfl_down_sync(FULLMASK, cnt, s);
        }
        if (lane == 0) wr[w] = make_float4(num, den, se, cnt);
        __syncthreads();
        if (t < 8) {
            float4 v4 = wr[t];
            float a0 = v4.x, a1 = v4.y, a2 = v4.z, a3 = v4.w;
            #pragma unroll
            for (int s = 4; s > 0; s >>= 1) {
                a0 += __shfl_down_sync(0xffu, a0, s);
                a1 += __shfl_down_sync(0xffu, a1, s);
                a2 += __shfl_down_sync(0xffu, a2, s);
                a3 += __shfl_down_sync(0xffu, a3, s);
            }
            if (t == 0) {
                atomicAdd(&g_lig_num[b], a0);
                atomicAdd(&g_lig_den[b], a1);
                atomicAdd(&g_lig_se[b],  a2);
                atomicAdd(&g_lig_cnt[b], a3);
            }
        }
    } else {
        // ======================= sidechain (shfl-based, 8 groups/warp) =======================
        if (t < 4) bacc[t] = 0.f;
        __syncthreads();

        const int h = (lane >> 4);          // half-warp id
        const int a = lane & 15;            // atom slot
        const bool av = a < A;
        const unsigned int gbase = (unsigned int)(bid - LIG_BLOCKS) * SC_GROUPS_PER_BLOCK + w * 8;

        float acc_gs = 0.f, acc_gc = 0.f, acc_mnum = 0.f, acc_mden = 0.f;

        #pragma unroll 1
        for (int it2 = 0; it2 < 4; ++it2) {
            const unsigned int g = gbase + it2 * 2 + h;

            float px=0.f, py=0.f, pz=0.f, tx=0.f, ty=0.f, tz=0.f;
            float m = 0.f, mnum = 0.f;
            if (av) {
                const float* Pg = scp + (size_t)g * (A*3) + a*3;
                const float* Tg = sct + (size_t)g * (A*3) + a*3;
                px = Pg[0]; py = Pg[1]; pz = Pg[2];
                tx = Tg[0]; ty = Tg[1]; tz = Tg[2];
                m = (am[(size_t)g * A + a] != 0u) ? 1.f : 0.f;
                float dx = px - tx, dy = py - ty, dz = pz - tz;
                mnum = m * (dx*dx + dy*dy + dz*dz) * (1.f/3.f);
                if (m == 0.f) tx += 1e3f + 48.f * (float)a;
            }
            const unsigned int bal = __ballot_sync(FULLMASK, av && m != 0.f);
            float pw = px*px + py*py + pz*pz;
            float tw = tx*tx + ty*ty + tz*tz;

            float num = 0.f, den = 0.f;
            int j = a;
            #pragma unroll
            for (int d = 1; d <= 7; ++d) {
                j = (j + 1 == A) ? 0 : j + 1;          // (a+d) mod 14
                int src = (lane & 16) | j;
                float qx = __shfl_sync(FULLMASK, px, src);
                float qy = __shfl_sync(FULLMASK, py, src);
                float qz = __shfl_sync(FULLMASK, pz, src);
                float qw = __shfl_sync(FULLMASK, pw, src);
                float sx = __shfl_sync(FULLMASK, tx, src);
                float sy = __shfl_sync(FULLMASK, ty, src);
                float sz = __shfl_sync(FULLMASK, tz, src);
                float sw = __shfl_sync(FULLMASK, tw, src);
                float dp = px*qx; dp = fmaf(py, qy, dp); dp = fmaf(pz, qz, dp);
                float dt = tx*sx; dt = fmaf(ty, sy, dt); dt = fmaf(tz, sz, dt);
                float psq = fmaf(-2.f, dp, pw + qw);
                float tsq = fmaf(-2.f, dt, tw + sw);
                float pe = fmaxf(psq, EPSV);
                float v = (pe + tsq) - 2.f * fast_sqrt(pe * tsq);
                bool act = (d < 7) ? av : (a < 7);
                if (act && tsq > 0.f && tsq <= CUT2) { num += v; den += 1.f; }
            }

            // reduce within each 16-lane segment
            #pragma unroll
            for (int s = 8; s > 0; s >>= 1) {
                num  += __shfl_down_sync(FULLMASK, num,  s, 16);
                den  += __shfl_down_sync(FULLMASK, den,  s, 16);
                mnum += __shfl_down_sync(FULLMASK, mnum, s, 16);
            }
            float gs = 0.f, gc = 0.f;
            if (a == 0 && den > 0.f) { gs = num / den; gc = 1.f; }
            gs   += __shfl_down_sync(FULLMASK, gs,   16);
            gc   += __shfl_down_sync(FULLMASK, gc,   16);
            mnum += __shfl_down_sync(FULLMASK, mnum, 16);
            if (lane == 0) {
                acc_gs   += gs;
                acc_gc   += gc;
                acc_mnum += mnum;
                acc_mden += (float)__popc(bal);
            }
        }

        if (lane == 0) {
            atomicAdd(&bacc[0], acc_gs);
            atomicAdd(&bacc[1], acc_gc);
            atomicAdd(&bacc[2], acc_mnum);
            atomicAdd(&bacc[3], acc_mden);
        }
        __syncthreads();
        if (t < 4) atomicAdd(&g_slots[t][bid & (NSLOT - 1)], bacc[t]);
    }

    // ======================= last-block finalization =======================
    __threadfence();
    if (t == 0) s_islast = (atomicAdd(&g_ticket, 1u) == (unsigned)(GRID - 1)) ? 1u : 0u;
    __syncthreads();
    if (!s_islast) return;

    float lig = 0.f, ld = 0.f, has = 0.f;
    if (t < B) {
        float sev = __ldcg(&g_lig_se[t]);
        float cn  = __ldcg(&g_lig_cnt[t]);
        float nu  = __ldcg(&g_lig_num[t]);
        float de  = __ldcg(&g_lig_den[t]);
        lig = sev / (3.f * fmaxf(cn, 1.f));
        if (de > 0.f) { ld = nu / de; has = 1.f; }
    }
    #pragma unroll
    for (int s = 16; s > 0; s >>= 1) {
        lig += __shfl_down_sync(FULLMASK, lig, s);
        ld  += __shfl_down_sync(FULLMASK, ld,  s);
        has += __shfl_down_sync(FULLMASK, has, s);
    }
    if (lane == 0 && t < B) { fin[0][w] = lig; fin[1][w] = ld; fin[2][w] = has; }

    if (t < NSLOT) {
        float s0 = __ldcg(&g_slots[0][t]);
        float s1 = __ldcg(&g_slots[1][t]);
        float s2 = __ldcg(&g_slots[2][t]);
        float s3 = __ldcg(&g_slots[3][t]);
        #pragma unroll
        for (int s = 16; s > 0; s >>= 1) {
            s0 += __shfl_down_sync(FULLMASK, s0, s);
            s1 += __shfl_down_sync(FULLMASK, s1, s);
            s2 += __shfl_down_sync(FULLMASK, s2, s);
            s3 += __shfl_down_sync(FULLMASK, s3, s);
        }
        if (t == 0) { sl[0] = s0; sl[1] = s1; sl[2] = s2; sl[3] = s3; }
    }
    __syncthreads();

    // reset scratch for next graph replay
    if (t < B) {
        g_lig_num[t] = 0.f; g_lig_den[t] = 0.f;
        g_lig_se[t]  = 0.f; g_lig_cnt[t] = 0.f;
    }
    if (t < 4 * NSLOT) g_slots[t >> 5][t & (NSLOT - 1)] = 0.f;
    if (t == 1) g_ticket = 0u;

    if (t == 0) {
        float ligand_loss = (fin[0][0] + fin[0][1]) * (1.f / 64.f);
        float hs = fin[2][0] + fin[2][1];
        float ligand_dist = (fin[1][0] + fin[1][1]) / fmaxf(hs, 1.f);
        float sc  = sl[2] / fmaxf(sl[3], 1.f);
        float scd = sl[0] / fmaxf(sl[1], 1.f);
        float total = ligand_loss + 0.2f * ligand_dist + 0.5f * sc + 0.1f * scd;
        for (int k = 0; k < out_size; ++k) out[k] = total;
    }
}

extern "C" void kernel_launch(void* const* d_in, const int* in_sizes, int n_in,
                              void* d_out, int out_size) {
    const float* lp  = (const float*)d_in[0];
    const float* lt  = (const float*)d_in[1];
    const float* scp = (const float*)d_in[2];
    const float* sct = (const float*)d_in[3];
    const unsigned int* lm = (const unsigned int*)d_in[4];
    const unsigned int* am = (const unsigned int*)d_in[5];
    (void)in_sizes; (void)n_in;

    fused_kernel<<<GRID, 256>>>(lp, lt, scp, sct, lm, am, (float*)d_out, out_size);
}